// round 5
// baseline (speedup 1.0000x reference)
#include <cuda_runtime.h>
#include <cuda_bf16.h>
#include <cstdint>

// Problem shape: A [64, 2048, 64], B [64, 64, 2048], out [64, 2048, 2048] (batch=4*16 flattened)
#define NBATCH 64
#define SDIM   2048
#define TDIM   2048
#define DDIM   64
#define NA_EL  (NBATCH * SDIM * DDIM)   // 8388608
#define NB_EL  (NBATCH * DDIM * TDIM)   // 8388608
#define MM_BLOCKS 256                   // minmax blocks per tensor

// ---- device-global state (scratch; no allocations allowed) ----
__device__ float g_pmin[2][MM_BLOCKS], g_pmax[2][MM_BLOCKS];
__device__ float g_scale;
__device__ __nv_bfloat16 g_Aq[NA_EL];
__device__ __nv_bfloat16 g_Bq[NB_EL];

// ---- pass 1: per-tensor min/max partials (deterministic, no atomics, no reset) ----
// grid (MM_BLOCKS, 1, 2): z=0 -> A, z=1 -> B. init 0 matches min(.,0)/max(.,0).
__global__ void __launch_bounds__(256) k_minmax(const float* __restrict__ A,
                                               const float* __restrict__ B) {
    const int sel = blockIdx.z;
    const float4* x4 = (const float4*)(sel ? B : A);
    const int n4 = NA_EL / 4;
    float vmin = 0.0f, vmax = 0.0f;
    for (int i = blockIdx.x * blockDim.x + threadIdx.x; i < n4;
         i += MM_BLOCKS * blockDim.x) {
        float4 v = x4[i];
        vmin = fminf(vmin, fminf(fminf(v.x, v.y), fminf(v.z, v.w)));
        vmax = fmaxf(vmax, fmaxf(fmaxf(v.x, v.y), fmaxf(v.z, v.w)));
    }
    #pragma unroll
    for (int o = 16; o > 0; o >>= 1) {
        vmin = fminf(vmin, __shfl_xor_sync(0xffffffffu, vmin, o));
        vmax = fmaxf(vmax, __shfl_xor_sync(0xffffffffu, vmax, o));
    }
    __shared__ float smin[8], smax[8];
    int wid = threadIdx.x >> 5, lane = threadIdx.x & 31;
    if (lane == 0) { smin[wid] = vmin; smax[wid] = vmax; }
    __syncthreads();
    if (threadIdx.x == 0) {
        float m = smin[0], M = smax[0];
        #pragma unroll
        for (int w = 1; w < 8; w++) { m = fminf(m, smin[w]); M = fmaxf(M, smax[w]); }
        g_pmin[sel][blockIdx.x] = m;
        g_pmax[sel][blockIdx.x] = M;
    }
}

// ---- pass 2: quant params (recomputed per block; deterministic) + fake-quant ----
// Quantize to INTEGER-valued bf16 (exact: |q-zp| <= 255 < 2^8).
// grid (2048, 1, 2): z=0 -> A, z=1 -> B.
__global__ void __launch_bounds__(256) k_quant(const float* __restrict__ A,
                                               const float* __restrict__ B) {
    const int t = threadIdx.x;
    // In-block reduction of the 256 partials for both tensors (L2 hits, ~free)
    float mA = g_pmin[0][t], MA = g_pmax[0][t];
    float mB = g_pmin[1][t], MB = g_pmax[1][t];
    #pragma unroll
    for (int o = 16; o > 0; o >>= 1) {
        mA = fminf(mA, __shfl_xor_sync(0xffffffffu, mA, o));
        MA = fmaxf(MA, __shfl_xor_sync(0xffffffffu, MA, o));
        mB = fminf(mB, __shfl_xor_sync(0xffffffffu, mB, o));
        MB = fmaxf(MB, __shfl_xor_sync(0xffffffffu, MB, o));
    }
    __shared__ float sred[4][8];
    __shared__ float s_delta, s_zp;
    int wid = t >> 5, lane = t & 31;
    if (lane == 0) { sred[0][wid] = mA; sred[1][wid] = MA; sred[2][wid] = mB; sred[3][wid] = MB; }
    __syncthreads();
    if (t == 0) {
        float minA = sred[0][0], maxA = sred[1][0], minB = sred[2][0], maxB = sred[3][0];
        #pragma unroll
        for (int w = 1; w < 8; w++) {
            minA = fminf(minA, sred[0][w]); maxA = fmaxf(maxA, sred[1][w]);
            minB = fminf(minB, sred[2][w]); maxB = fmaxf(maxB, sred[3][w]);
        }
        float dA = fmaxf(__fdiv_rn(maxA - minA, 255.0f), 1e-8f);
        float dB = fmaxf(__fdiv_rn(maxB - minB, 255.0f), 1e-8f);
        if (blockIdx.z == 0) {
            s_delta = dA;
            s_zp = rintf(__fdiv_rn(-minA, dA));
        } else {
            s_delta = dB;
            s_zp = rintf(__fdiv_rn(-minB, dB));
        }
        if (blockIdx.x == 0 && blockIdx.z == 0) g_scale = dA * dB;
    }
    __syncthreads();
    const float delta = s_delta, zp = s_zp;

    const int sel = blockIdx.z;
    const float4* x4 = (const float4*)(sel ? B : A);
    uint2* o2 = (uint2*)(sel ? g_Bq : g_Aq);
    const int n4 = NA_EL / 4;
    for (int i = blockIdx.x * blockDim.x + t; i < n4; i += 2048 * 256) {
        float4 v = x4[i];
        float q0 = fminf(fmaxf(rintf(__fdiv_rn(v.x, delta)) + zp, 0.0f), 255.0f) - zp;
        float q1 = fminf(fmaxf(rintf(__fdiv_rn(v.y, delta)) + zp, 0.0f), 255.0f) - zp;
        float q2 = fminf(fmaxf(rintf(__fdiv_rn(v.z, delta)) + zp, 0.0f), 255.0f) - zp;
        float q3 = fminf(fmaxf(rintf(__fdiv_rn(v.w, delta)) + zp, 0.0f), 255.0f) - zp;
        __nv_bfloat162 p0 = __floats2bfloat162_rn(q0, q1);
        __nv_bfloat162 p1 = __floats2bfloat162_rn(q2, q3);
        uint2 u;
        u.x = *(uint32_t*)&p0;
        u.y = *(uint32_t*)&p1;
        o2[i] = u;
    }
}

// ---- pass 3: batched GEMM, CTA tile 128x128, K=64 single load, mma.m16n8k16 ----
// grid (16 ntiles, 16 mtiles, 64 batches), 256 threads = 8 warps (2x4 warp grid)
// Epilogue: lane-pair shfl merge -> STG.128 (halves store-issue cost vs STG.64)
__global__ void __launch_bounds__(256, 2) k_gemm(float* __restrict__ out) {
    __shared__ __nv_bfloat16 sA[128][72];   // 64 cols + 8 pad (16B row shift -> no LDSM conflicts)
    __shared__ __nv_bfloat16 sB[64][136];   // 128 cols + 8 pad

    const int b  = blockIdx.z;
    const int m0 = blockIdx.y * 128;
    const int n0 = blockIdx.x * 128;
    const __nv_bfloat16* Ab = g_Aq + (size_t)b * SDIM * DDIM;
    const __nv_bfloat16* Bb = g_Bq + (size_t)b * DDIM * TDIM;
    float* ob = out + (size_t)b * SDIM * TDIM;
    const int tid = threadIdx.x;

    // load A tile: 128 rows x 64 cols = 1024 x 16B chunks
    #pragma unroll
    for (int it = 0; it < 4; it++) {
        int id = tid + it * 256;
        int r = id >> 3, c = (id & 7) * 8;
        *(uint4*)&sA[r][c] = *(const uint4*)(Ab + (m0 + r) * DDIM + c);
    }
    // load B tile: 64 rows x 128 cols = 1024 x 16B chunks
    #pragma unroll
    for (int it = 0; it < 4; it++) {
        int id = tid + it * 256;
        int r = id >> 4, c = (id & 15) * 8;
        *(uint4*)&sB[r][c] = *(const uint4*)(Bb + r * TDIM + n0 + c);
    }
    __syncthreads();

    const int warp = tid >> 5, lane = tid & 31;
    const int wm = warp >> 2;      // 0..1 -> 64 rows each
    const int wn = warp & 3;       // 0..3 -> 32 cols each

    float acc[4][4][4];
    #pragma unroll
    for (int mi = 0; mi < 4; mi++)
        #pragma unroll
        for (int ni = 0; ni < 4; ni++)
            #pragma unroll
            for (int q = 0; q < 4; q++) acc[mi][ni][q] = 0.0f;

    #pragma unroll
    for (int ks = 0; ks < 4; ks++) {
        const int k0 = ks * 16;
        // A fragments: 4 m-tiles of 16x16 via ldmatrix.x4
        uint32_t af[4][4];
        #pragma unroll
        for (int mi = 0; mi < 4; mi++) {
            int r = wm * 64 + mi * 16 + (lane & 15);
            int c = k0 + (lane >> 4) * 8;
            uint32_t addr = (uint32_t)__cvta_generic_to_shared(&sA[r][c]);
            asm volatile(
                "ldmatrix.sync.aligned.m8n8.x4.shared.b16 {%0,%1,%2,%3}, [%4];"
                : "=r"(af[mi][0]), "=r"(af[mi][1]), "=r"(af[mi][2]), "=r"(af[mi][3])
                : "r"(addr));
        }
        // B fragments: 2 x ldmatrix.x4.trans, each covers 2 n-tiles (16 cols)
        uint32_t bf[4][2];
        #pragma unroll
        for (int nj = 0; nj < 2; nj++) {
            int r = k0 + (lane & 7) + ((lane >> 3) & 1) * 8;
            int c = wn * 32 + nj * 16 + (lane >> 4) * 8;
            uint32_t addr = (uint32_t)__cvta_generic_to_shared(&sB[r][c]);
            uint32_t t0, t1, t2, t3;
            asm volatile(
                "ldmatrix.sync.aligned.m8n8.x4.trans.shared.b16 {%0,%1,%2,%3}, [%4];"
                : "=r"(t0), "=r"(t1), "=r"(t2), "=r"(t3)
                : "r"(addr));
            bf[nj * 2 + 0][0] = t0; bf[nj * 2 + 0][1] = t1;
            bf[nj * 2 + 1][0] = t2; bf[nj * 2 + 1][1] = t3;
        }
        #pragma unroll
        for (int mi = 0; mi < 4; mi++)
            #pragma unroll
            for (int ni = 0; ni < 4; ni++) {
                asm volatile(
                    "mma.sync.aligned.m16n8k16.row.col.f32.bf16.bf16.f32 "
                    "{%0,%1,%2,%3}, {%4,%5,%6,%7}, {%8,%9}, {%0,%1,%2,%3};"
                    : "+f"(acc[mi][ni][0]), "+f"(acc[mi][ni][1]),
                      "+f"(acc[mi][ni][2]), "+f"(acc[mi][ni][3])
                    : "r"(af[mi][0]), "r"(af[mi][1]), "r"(af[mi][2]), "r"(af[mi][3]),
                      "r"(bf[ni][0]), "r"(bf[ni][1]));
            }
    }

    // Epilogue: lane-pair merge -> STG.128.
    // In m16n8 layout, quad lanes j=lane&3 hold col pairs {2j,2j+1}. Lanes l and
    // l^1 together hold 4 consecutive cols of the same row. Exchange via shfl:
    // even-j lane stores float4 of row r; odd-j lane stores float4 of row r+8.
    const float s = g_scale;
    const int jj = lane & 3;
    const int odd = jj & 1;
    const int cb = (jj >> 1) << 2;               // 0 or 4 within the 8-wide tile
    #pragma unroll
    for (int mi = 0; mi < 4; mi++) {
        #pragma unroll
        for (int ni = 0; ni < 4; ni++) {
            float a0 = acc[mi][ni][0] * s;
            float a1 = acc[mi][ni][1] * s;
            float a2 = acc[mi][ni][2] * s;
            float a3 = acc[mi][ni][3] * s;
            float t0 = __shfl_xor_sync(0xffffffffu, a0, 1);
            float t1 = __shfl_xor_sync(0xffffffffu, a1, 1);
            float t2 = __shfl_xor_sync(0xffffffffu, a2, 1);
            float t3 = __shfl_xor_sync(0xffffffffu, a3, 1);
            int r = m0 + wm * 64 + mi * 16 + (lane >> 2) + (odd ? 8 : 0);
            int c = n0 + wn * 32 + ni * 8 + cb;
            float4 v = odd ? make_float4(t2, t3, a2, a3)
                           : make_float4(a0, a1, t0, t1);
            *(float4*)&ob[(size_t)r * TDIM + c] = v;
        }
    }
}

extern "C" void kernel_launch(void* const* d_in, const int* in_sizes, int n_in,
                              void* d_out, int out_size) {
    const float* A = (const float*)d_in[0];
    const float* B = (const float*)d_in[1];
    float* out = (float*)d_out;

    k_minmax<<<dim3(MM_BLOCKS, 1, 2), 256>>>(A, B);
    k_quant<<<dim3(2048, 1, 2), 256>>>(A, B);
    k_gemm<<<dim3(16, 16, 64), 256>>>(out);
}

// round 6
// speedup vs baseline: 1.2572x; 1.2572x over previous
#include <cuda_runtime.h>
#include <cuda_bf16.h>
#include <cstdint>

// Problem shape: A [64, 2048, 64], B [64, 64, 2048], out [64, 2048, 2048] (batch=4*16 flattened)
#define NBATCH 64
#define SDIM   2048
#define TDIM   2048
#define DDIM   64
#define NA_EL  (NBATCH * SDIM * DDIM)   // 8388608
#define NB_EL  (NBATCH * DDIM * TDIM)   // 8388608
#define MM_BLOCKS 256                   // minmax blocks per tensor
#define NTILES  (NBATCH * 16 * 16)      // 16384 output tiles of 128x128
#define GEMM_GRID 296                   // 2 CTAs per SM (148 SMs)

// ---- device-global state (scratch; no allocations allowed) ----
__device__ float g_pmin[2][MM_BLOCKS], g_pmax[2][MM_BLOCKS];
__device__ float g_scale;
__device__ __nv_bfloat16 g_Aq[NA_EL];
__device__ __nv_bfloat16 g_Bq[NB_EL];

// ---- pass 1: per-tensor min/max partials (deterministic, no atomics, no reset) ----
// grid (MM_BLOCKS, 1, 2): z=0 -> A, z=1 -> B. init 0 matches min(.,0)/max(.,0).
__global__ void __launch_bounds__(256) k_minmax(const float* __restrict__ A,
                                               const float* __restrict__ B) {
    const int sel = blockIdx.z;
    const float4* x4 = (const float4*)(sel ? B : A);
    const int n4 = NA_EL / 4;
    float vmin = 0.0f, vmax = 0.0f;
    for (int i = blockIdx.x * blockDim.x + threadIdx.x; i < n4;
         i += MM_BLOCKS * blockDim.x) {
        float4 v = x4[i];
        vmin = fminf(vmin, fminf(fminf(v.x, v.y), fminf(v.z, v.w)));
        vmax = fmaxf(vmax, fmaxf(fmaxf(v.x, v.y), fmaxf(v.z, v.w)));
    }
    #pragma unroll
    for (int o = 16; o > 0; o >>= 1) {
        vmin = fminf(vmin, __shfl_xor_sync(0xffffffffu, vmin, o));
        vmax = fmaxf(vmax, __shfl_xor_sync(0xffffffffu, vmax, o));
    }
    __shared__ float smin[8], smax[8];
    int wid = threadIdx.x >> 5, lane = threadIdx.x & 31;
    if (lane == 0) { smin[wid] = vmin; smax[wid] = vmax; }
    __syncthreads();
    if (threadIdx.x == 0) {
        float m = smin[0], M = smax[0];
        #pragma unroll
        for (int w = 1; w < 8; w++) { m = fminf(m, smin[w]); M = fmaxf(M, smax[w]); }
        g_pmin[sel][blockIdx.x] = m;
        g_pmax[sel][blockIdx.x] = M;
    }
}

// ---- pass 2: quant params (recomputed per block; deterministic) + fake-quant ----
// Quantize to INTEGER-valued bf16 (exact: |q-zp| <= 255 < 2^8).
// grid (2048, 1, 2): z=0 -> A, z=1 -> B.
__global__ void __launch_bounds__(256) k_quant(const float* __restrict__ A,
                                               const float* __restrict__ B) {
    const int t = threadIdx.x;
    float mA = g_pmin[0][t], MA = g_pmax[0][t];
    float mB = g_pmin[1][t], MB = g_pmax[1][t];
    #pragma unroll
    for (int o = 16; o > 0; o >>= 1) {
        mA = fminf(mA, __shfl_xor_sync(0xffffffffu, mA, o));
        MA = fmaxf(MA, __shfl_xor_sync(0xffffffffu, MA, o));
        mB = fminf(mB, __shfl_xor_sync(0xffffffffu, mB, o));
        MB = fmaxf(MB, __shfl_xor_sync(0xffffffffu, MB, o));
    }
    __shared__ float sred[4][8];
    __shared__ float s_delta, s_zp;
    int wid = t >> 5, lane = t & 31;
    if (lane == 0) { sred[0][wid] = mA; sred[1][wid] = MA; sred[2][wid] = mB; sred[3][wid] = MB; }
    __syncthreads();
    if (t == 0) {
        float minA = sred[0][0], maxA = sred[1][0], minB = sred[2][0], maxB = sred[3][0];
        #pragma unroll
        for (int w = 1; w < 8; w++) {
            minA = fminf(minA, sred[0][w]); maxA = fmaxf(maxA, sred[1][w]);
            minB = fminf(minB, sred[2][w]); maxB = fmaxf(maxB, sred[3][w]);
        }
        float dA = fmaxf(__fdiv_rn(maxA - minA, 255.0f), 1e-8f);
        float dB = fmaxf(__fdiv_rn(maxB - minB, 255.0f), 1e-8f);
        if (blockIdx.z == 0) {
            s_delta = dA;
            s_zp = rintf(__fdiv_rn(-minA, dA));
        } else {
            s_delta = dB;
            s_zp = rintf(__fdiv_rn(-minB, dB));
        }
        if (blockIdx.x == 0 && blockIdx.z == 0) g_scale = dA * dB;
    }
    __syncthreads();
    const float delta = s_delta, zp = s_zp;

    const int sel = blockIdx.z;
    const float4* x4 = (const float4*)(sel ? B : A);
    uint2* o2 = (uint2*)(sel ? g_Bq : g_Aq);
    const int n4 = NA_EL / 4;
    for (int i = blockIdx.x * blockDim.x + t; i < n4; i += 2048 * 256) {
        float4 v = x4[i];
        float q0 = fminf(fmaxf(rintf(__fdiv_rn(v.x, delta)) + zp, 0.0f), 255.0f) - zp;
        float q1 = fminf(fmaxf(rintf(__fdiv_rn(v.y, delta)) + zp, 0.0f), 255.0f) - zp;
        float q2 = fminf(fmaxf(rintf(__fdiv_rn(v.z, delta)) + zp, 0.0f), 255.0f) - zp;
        float q3 = fminf(fmaxf(rintf(__fdiv_rn(v.w, delta)) + zp, 0.0f), 255.0f) - zp;
        __nv_bfloat162 p0 = __floats2bfloat162_rn(q0, q1);
        __nv_bfloat162 p1 = __floats2bfloat162_rn(q2, q3);
        uint2 u;
        u.x = *(uint32_t*)&p0;
        u.y = *(uint32_t*)&p1;
        o2[i] = u;
    }
}

// ---- pass 3: persistent batched GEMM, CTA tile 128x128, double-buffered cp.async ----
// 296 CTAs (2/SM), each loops over tiles with stride gridDim.x. Prefetch of tile
// i+1 overlaps MMA + store drain of tile i (intra-CTA phase overlap).
#define SA_ROWS 128
#define SA_COLS 72     // 64 + 8 pad (16B row shift -> no LDSM conflicts)
#define SB_ROWS 64
#define SB_COLS 136    // 128 + 8 pad
#define SA_BYTES (SA_ROWS * SA_COLS * 2)
#define SB_BYTES (SB_ROWS * SB_COLS * 2)
#define SMEM_DYN (2 * (SA_BYTES + SB_BYTES))   // 71680 B

__device__ __forceinline__ void cpa16(void* dst, const void* src) {
    uint32_t d = (uint32_t)__cvta_generic_to_shared(dst);
    asm volatile("cp.async.cg.shared.global [%0], [%1], 16;" :: "r"(d), "l"(src));
}

__global__ void __launch_bounds__(256, 2) k_gemm(float* __restrict__ out) {
    extern __shared__ char smem_raw[];
    typedef __nv_bfloat16 (*SAp)[SA_ROWS][SA_COLS];
    typedef __nv_bfloat16 (*SBp)[SB_ROWS][SB_COLS];
    SAp sA = (SAp)smem_raw;                              // [2][128][72]
    SBp sB = (SBp)(smem_raw + 2 * SA_BYTES);             // [2][64][136]

    const int tid = threadIdx.x;
    const int warp = tid >> 5, lane = tid & 31;
    const int wm = warp >> 2;      // 0..1 -> 64 rows each
    const int wn = warp & 3;       // 0..3 -> 32 cols each

    // per-thread load slots (8 x 16B chunks: 4 for A, 4 for B)
    const int ar = tid >> 3, ac = (tid & 7) * 8;          // A: rows ar, ar+32, ar+64, ar+96
    const int br = tid >> 4, bc = (tid & 15) * 8;         // B: rows br, br+16, br+32, br+48

    auto load_tiles = [&](int buf, int t) {
        int b  = t >> 8;
        int m0 = ((t >> 4) & 15) * 128;
        int n0 = (t & 15) * 128;
        const __nv_bfloat16* Ab = g_Aq + (size_t)b * SDIM * DDIM + (size_t)m0 * DDIM;
        const __nv_bfloat16* Bb = g_Bq + (size_t)b * DDIM * TDIM + n0;
        #pragma unroll
        for (int it = 0; it < 4; it++)
            cpa16(&sA[buf][ar + it * 32][ac], Ab + (ar + it * 32) * DDIM + ac);
        #pragma unroll
        for (int it = 0; it < 4; it++)
            cpa16(&sB[buf][br + it * 16][bc], Bb + (size_t)(br + it * 16) * TDIM + bc);
    };

    const float s = g_scale;

    int t = blockIdx.x;
    load_tiles(0, t);
    asm volatile("cp.async.commit_group;");
    int buf = 0;

    while (t < NTILES) {
        const int tn = t + GEMM_GRID;
        if (tn < NTILES) {
            load_tiles(buf ^ 1, tn);
            asm volatile("cp.async.commit_group;");
            asm volatile("cp.async.wait_group 1;");   // current tile's group done
        } else {
            asm volatile("cp.async.wait_group 0;");
        }
        __syncthreads();

        float acc[4][4][4];
        #pragma unroll
        for (int mi = 0; mi < 4; mi++)
            #pragma unroll
            for (int ni = 0; ni < 4; ni++)
                #pragma unroll
                for (int q = 0; q < 4; q++) acc[mi][ni][q] = 0.0f;

        #pragma unroll
        for (int ks = 0; ks < 4; ks++) {
            const int k0 = ks * 16;
            uint32_t af[4][4];
            #pragma unroll
            for (int mi = 0; mi < 4; mi++) {
                int r = wm * 64 + mi * 16 + (lane & 15);
                int c = k0 + (lane >> 4) * 8;
                uint32_t addr = (uint32_t)__cvta_generic_to_shared(&sA[buf][r][c]);
                asm volatile(
                    "ldmatrix.sync.aligned.m8n8.x4.shared.b16 {%0,%1,%2,%3}, [%4];"
                    : "=r"(af[mi][0]), "=r"(af[mi][1]), "=r"(af[mi][2]), "=r"(af[mi][3])
                    : "r"(addr));
            }
            uint32_t bf[4][2];
            #pragma unroll
            for (int nj = 0; nj < 2; nj++) {
                int r = k0 + (lane & 7) + ((lane >> 3) & 1) * 8;
                int c = wn * 32 + nj * 16 + (lane >> 4) * 8;
                uint32_t addr = (uint32_t)__cvta_generic_to_shared(&sB[buf][r][c]);
                uint32_t t0, t1, t2, t3;
                asm volatile(
                    "ldmatrix.sync.aligned.m8n8.x4.trans.shared.b16 {%0,%1,%2,%3}, [%4];"
                    : "=r"(t0), "=r"(t1), "=r"(t2), "=r"(t3)
                    : "r"(addr));
                bf[nj * 2 + 0][0] = t0; bf[nj * 2 + 0][1] = t1;
                bf[nj * 2 + 1][0] = t2; bf[nj * 2 + 1][1] = t3;
            }
            #pragma unroll
            for (int mi = 0; mi < 4; mi++)
                #pragma unroll
                for (int ni = 0; ni < 4; ni++) {
                    asm volatile(
                        "mma.sync.aligned.m16n8k16.row.col.f32.bf16.bf16.f32 "
                        "{%0,%1,%2,%3}, {%4,%5,%6,%7}, {%8,%9}, {%0,%1,%2,%3};"
                        : "+f"(acc[mi][ni][0]), "+f"(acc[mi][ni][1]),
                          "+f"(acc[mi][ni][2]), "+f"(acc[mi][ni][3])
                        : "r"(af[mi][0]), "r"(af[mi][1]), "r"(af[mi][2]), "r"(af[mi][3]),
                          "r"(bf[ni][0]), "r"(bf[ni][1]));
                }
        }
        __syncthreads();   // all warps done reading buf before next iter refills it

        // epilogue (stores drain while next iteration computes)
        {
            int b  = t >> 8;
            int m0 = ((t >> 4) & 15) * 128;
            int n0 = (t & 15) * 128;
            float* ob = out + (size_t)b * SDIM * TDIM;
            #pragma unroll
            for (int mi = 0; mi < 4; mi++) {
                #pragma unroll
                for (int ni = 0; ni < 4; ni++) {
                    int r = m0 + wm * 64 + mi * 16 + (lane >> 2);
                    int c = n0 + wn * 32 + ni * 8 + (lane & 3) * 2;
                    float2 v0 = make_float2(acc[mi][ni][0] * s, acc[mi][ni][1] * s);
                    float2 v1 = make_float2(acc[mi][ni][2] * s, acc[mi][ni][3] * s);
                    *(float2*)&ob[(size_t)r * TDIM + c]       = v0;
                    *(float2*)&ob[(size_t)(r + 8) * TDIM + c] = v1;
                }
            }
        }

        buf ^= 1;
        t = tn;
    }
}

extern "C" void kernel_launch(void* const* d_in, const int* in_sizes, int n_in,
                              void* d_out, int out_size) {
    const float* A = (const float*)d_in[0];
    const float* B = (const float*)d_in[1];
    float* out = (float*)d_out;

    static int configured = 0;
    if (!configured) {
        cudaFuncSetAttribute(k_gemm, cudaFuncAttributeMaxDynamicSharedMemorySize, SMEM_DYN);
        configured = 1;
    }

    k_minmax<<<dim3(MM_BLOCKS, 1, 2), 256>>>(A, B);
    k_quant<<<dim3(2048, 1, 2), 256>>>(A, B);
    k_gemm<<<GEMM_GRID, 256, SMEM_DYN>>>(out);
}

// round 7
// speedup vs baseline: 1.2867x; 1.0235x over previous
#include <cuda_runtime.h>
#include <cuda_bf16.h>
#include <cstdint>

// Problem shape: A [64, 2048, 64], B [64, 64, 2048], out [64, 2048, 2048] (batch=4*16 flattened)
#define NBATCH 64
#define SDIM   2048
#define TDIM   2048
#define DDIM   64
#define NA_EL  (NBATCH * SDIM * DDIM)   // 8388608
#define NB_EL  (NBATCH * DDIM * TDIM)   // 8388608
#define MM_BLOCKS 256                   // minmax blocks per tensor
#define NTILES  (NBATCH * 16 * 16)      // 16384 output tiles of 128x128
#define GEMM_GRID 296                   // 2 CTAs per SM (148 SMs)

// ---- device-global state (scratch; no allocations allowed) ----
__device__ float g_pmin[2][MM_BLOCKS], g_pmax[2][MM_BLOCKS];
__device__ float g_scale;
__device__ __nv_bfloat16 g_Aq[NA_EL];
__device__ __nv_bfloat16 g_Bq[NB_EL];

// ---- pass 1: per-tensor min/max partials (deterministic, no atomics, no reset) ----
__global__ void __launch_bounds__(256) k_minmax(const float* __restrict__ A,
                                               const float* __restrict__ B) {
    const int sel = blockIdx.z;
    const float4* x4 = (const float4*)(sel ? B : A);
    const int n4 = NA_EL / 4;
    float vmin = 0.0f, vmax = 0.0f;
    for (int i = blockIdx.x * blockDim.x + threadIdx.x; i < n4;
         i += MM_BLOCKS * blockDim.x) {
        float4 v = x4[i];
        vmin = fminf(vmin, fminf(fminf(v.x, v.y), fminf(v.z, v.w)));
        vmax = fmaxf(vmax, fmaxf(fmaxf(v.x, v.y), fmaxf(v.z, v.w)));
    }
    #pragma unroll
    for (int o = 16; o > 0; o >>= 1) {
        vmin = fminf(vmin, __shfl_xor_sync(0xffffffffu, vmin, o));
        vmax = fmaxf(vmax, __shfl_xor_sync(0xffffffffu, vmax, o));
    }
    __shared__ float smin[8], smax[8];
    int wid = threadIdx.x >> 5, lane = threadIdx.x & 31;
    if (lane == 0) { smin[wid] = vmin; smax[wid] = vmax; }
    __syncthreads();
    if (threadIdx.x == 0) {
        float m = smin[0], M = smax[0];
        #pragma unroll
        for (int w = 1; w < 8; w++) { m = fminf(m, smin[w]); M = fmaxf(M, smax[w]); }
        g_pmin[sel][blockIdx.x] = m;
        g_pmax[sel][blockIdx.x] = M;
    }
}

// ---- pass 2: quant params (recomputed per block; deterministic) + fake-quant ----
__global__ void __launch_bounds__(256) k_quant(const float* __restrict__ A,
                                               const float* __restrict__ B) {
    const int t = threadIdx.x;
    float mA = g_pmin[0][t], MA = g_pmax[0][t];
    float mB = g_pmin[1][t], MB = g_pmax[1][t];
    #pragma unroll
    for (int o = 16; o > 0; o >>= 1) {
        mA = fminf(mA, __shfl_xor_sync(0xffffffffu, mA, o));
        MA = fmaxf(MA, __shfl_xor_sync(0xffffffffu, MA, o));
        mB = fminf(mB, __shfl_xor_sync(0xffffffffu, mB, o));
        MB = fmaxf(MB, __shfl_xor_sync(0xffffffffu, MB, o));
    }
    __shared__ float sred[4][8];
    __shared__ float s_delta, s_zp;
    int wid = t >> 5, lane = t & 31;
    if (lane == 0) { sred[0][wid] = mA; sred[1][wid] = MA; sred[2][wid] = mB; sred[3][wid] = MB; }
    __syncthreads();
    if (t == 0) {
        float minA = sred[0][0], maxA = sred[1][0], minB = sred[2][0], maxB = sred[3][0];
        #pragma unroll
        for (int w = 1; w < 8; w++) {
            minA = fminf(minA, sred[0][w]); maxA = fmaxf(maxA, sred[1][w]);
            minB = fminf(minB, sred[2][w]); maxB = fmaxf(maxB, sred[3][w]);
        }
        float dA = fmaxf(__fdiv_rn(maxA - minA, 255.0f), 1e-8f);
        float dB = fmaxf(__fdiv_rn(maxB - minB, 255.0f), 1e-8f);
        if (blockIdx.z == 0) {
            s_delta = dA;
            s_zp = rintf(__fdiv_rn(-minA, dA));
        } else {
            s_delta = dB;
            s_zp = rintf(__fdiv_rn(-minB, dB));
        }
        if (blockIdx.x == 0 && blockIdx.z == 0) g_scale = dA * dB;
    }
    __syncthreads();
    const float delta = s_delta, zp = s_zp;

    const int sel = blockIdx.z;
    const float4* x4 = (const float4*)(sel ? B : A);
    uint2* o2 = (uint2*)(sel ? g_Bq : g_Aq);
    const int n4 = NA_EL / 4;
    for (int i = blockIdx.x * blockDim.x + t; i < n4; i += 2048 * 256) {
        float4 v = x4[i];
        float q0 = fminf(fmaxf(rintf(__fdiv_rn(v.x, delta)) + zp, 0.0f), 255.0f) - zp;
        float q1 = fminf(fmaxf(rintf(__fdiv_rn(v.y, delta)) + zp, 0.0f), 255.0f) - zp;
        float q2 = fminf(fmaxf(rintf(__fdiv_rn(v.z, delta)) + zp, 0.0f), 255.0f) - zp;
        float q3 = fminf(fmaxf(rintf(__fdiv_rn(v.w, delta)) + zp, 0.0f), 255.0f) - zp;
        __nv_bfloat162 p0 = __floats2bfloat162_rn(q0, q1);
        __nv_bfloat162 p1 = __floats2bfloat162_rn(q2, q3);
        uint2 u;
        u.x = *(uint32_t*)&p0;
        u.y = *(uint32_t*)&p1;
        o2[i] = u;
    }
}

// ---- pass 3: persistent batched GEMM, CTA tile 128x128, 3-stage cp.async ----
// 296 CTAs (2/SM). Prefetch depth 2, ONE barrier per tile iteration:
// after barrier in iter i all warps are inside iter i, so a lead warp filling
// stage (s+2)%3 can't collide with a lagging warp reading stage s or s+1.
#define SA_ROWS 128
#define SA_COLS 72     // 64 + 8 pad (16B row shift -> no LDSM conflicts)
#define SB_ROWS 64
#define SB_COLS 136    // 128 + 8 pad
#define SA_BYTES (SA_ROWS * SA_COLS * 2)
#define SB_BYTES (SB_ROWS * SB_COLS * 2)
#define STAGE_BYTES (SA_BYTES + SB_BYTES)      // 35840
#define NSTAGE 3
#define SMEM_DYN (NSTAGE * STAGE_BYTES)        // 107520 B (2 CTAs = 215KB <= 228KB)

__device__ __forceinline__ void cpa16(void* dst, const void* src) {
    uint32_t d = (uint32_t)__cvta_generic_to_shared(dst);
    asm volatile("cp.async.cg.shared.global [%0], [%1], 16;" :: "r"(d), "l"(src));
}

__global__ void __launch_bounds__(256, 2) k_gemm(float* __restrict__ out) {
    extern __shared__ char smem_raw[];

    const int tid = threadIdx.x;
    const int warp = tid >> 5, lane = tid & 31;
    const int wm = warp >> 2;      // 0..1 -> 64 rows each
    const int wn = warp & 3;       // 0..3 -> 32 cols each

    // per-thread load slots (8 x 16B chunks: 4 for A, 4 for B)
    const int ar = tid >> 3, ac = (tid & 7) * 8;          // A rows ar+{0,32,64,96}
    const int br = tid >> 4, bc = (tid & 15) * 8;         // B rows br+{0,16,32,48}

    auto stageA = [&](int st) -> __nv_bfloat16 (*)[SA_COLS] {
        return (__nv_bfloat16 (*)[SA_COLS])(smem_raw + st * STAGE_BYTES);
    };
    auto stageB = [&](int st) -> __nv_bfloat16 (*)[SB_COLS] {
        return (__nv_bfloat16 (*)[SB_COLS])(smem_raw + st * STAGE_BYTES + SA_BYTES);
    };

    auto load_tiles = [&](int st, int t) {
        int b  = t >> 8;
        int m0 = ((t >> 4) & 15) * 128;
        int n0 = (t & 15) * 128;
        const __nv_bfloat16* Ab = g_Aq + (size_t)b * SDIM * DDIM + (size_t)m0 * DDIM;
        const __nv_bfloat16* Bb = g_Bq + (size_t)b * DDIM * TDIM + n0;
        __nv_bfloat16 (*sA)[SA_COLS] = stageA(st);
        __nv_bfloat16 (*sB)[SB_COLS] = stageB(st);
        #pragma unroll
        for (int it = 0; it < 4; it++)
            cpa16(&sA[ar + it * 32][ac], Ab + (ar + it * 32) * DDIM + ac);
        #pragma unroll
        for (int it = 0; it < 4; it++)
            cpa16(&sB[br + it * 16][bc], Bb + (size_t)(br + it * 16) * TDIM + bc);
        asm volatile("cp.async.commit_group;");
    };

    const float s = g_scale;

    int t = blockIdx.x;
    int st = 0;
    if (t < NTILES) load_tiles(0, t);
    if (t + GEMM_GRID < NTILES) load_tiles(1, t + GEMM_GRID);

    while (t < NTILES) {
        if (t + GEMM_GRID < NTILES) {
            asm volatile("cp.async.wait_group 1;");   // this tile's group done
        } else {
            asm volatile("cp.async.wait_group 0;");
        }
        __syncthreads();   // single barrier per iteration

        __nv_bfloat16 (*sA)[SA_COLS] = stageA(st);
        __nv_bfloat16 (*sB)[SB_COLS] = stageB(st);

        float acc[4][4][4];
        #pragma unroll
        for (int mi = 0; mi < 4; mi++)
            #pragma unroll
            for (int ni = 0; ni < 4; ni++)
                #pragma unroll
                for (int q = 0; q < 4; q++) acc[mi][ni][q] = 0.0f;

        #pragma unroll
        for (int ks = 0; ks < 4; ks++) {
            const int k0 = ks * 16;
            uint32_t af[4][4];
            #pragma unroll
            for (int mi = 0; mi < 4; mi++) {
                int r = wm * 64 + mi * 16 + (lane & 15);
                int c = k0 + (lane >> 4) * 8;
                uint32_t addr = (uint32_t)__cvta_generic_to_shared(&sA[r][c]);
                asm volatile(
                    "ldmatrix.sync.aligned.m8n8.x4.shared.b16 {%0,%1,%2,%3}, [%4];"
                    : "=r"(af[mi][0]), "=r"(af[mi][1]), "=r"(af[mi][2]), "=r"(af[mi][3])
                    : "r"(addr));
            }
            uint32_t bf[4][2];
            #pragma unroll
            for (int nj = 0; nj < 2; nj++) {
                int r = k0 + (lane & 7) + ((lane >> 3) & 1) * 8;
                int c = wn * 32 + nj * 16 + (lane >> 4) * 8;
                uint32_t addr = (uint32_t)__cvta_generic_to_shared(&sB[r][c]);
                uint32_t t0, t1, t2, t3;
                asm volatile(
                    "ldmatrix.sync.aligned.m8n8.x4.trans.shared.b16 {%0,%1,%2,%3}, [%4];"
                    : "=r"(t0), "=r"(t1), "=r"(t2), "=r"(t3)
                    : "r"(addr));
                bf[nj * 2 + 0][0] = t0; bf[nj * 2 + 0][1] = t1;
                bf[nj * 2 + 1][0] = t2; bf[nj * 2 + 1][1] = t3;
            }
            #pragma unroll
            for (int mi = 0; mi < 4; mi++)
                #pragma unroll
                for (int ni = 0; ni < 4; ni++) {
                    asm volatile(
                        "mma.sync.aligned.m16n8k16.row.col.f32.bf16.bf16.f32 "
                        "{%0,%1,%2,%3}, {%4,%5,%6,%7}, {%8,%9}, {%0,%1,%2,%3};"
                        : "+f"(acc[mi][ni][0]), "+f"(acc[mi][ni][1]),
                          "+f"(acc[mi][ni][2]), "+f"(acc[mi][ni][3])
                        : "r"(af[mi][0]), "r"(af[mi][1]), "r"(af[mi][2]), "r"(af[mi][3]),
                          "r"(bf[ni][0]), "r"(bf[ni][1]));
                }
        }

        // epilogue stores (drain while loads for i+2 stream and next iter computes)
        {
            int b  = t >> 8;
            int m0 = ((t >> 4) & 15) * 128;
            int n0 = (t & 15) * 128;
            float* ob = out + (size_t)b * SDIM * TDIM;
            #pragma unroll
            for (int mi = 0; mi < 4; mi++) {
                #pragma unroll
                for (int ni = 0; ni < 4; ni++) {
                    int r = m0 + wm * 64 + mi * 16 + (lane >> 2);
                    int c = n0 + wn * 32 + ni * 8 + (lane & 3) * 2;
                    float2 v0 = make_float2(acc[mi][ni][0] * s, acc[mi][ni][1] * s);
                    float2 v1 = make_float2(acc[mi][ni][2] * s, acc[mi][ni][3] * s);
                    *(float2*)&ob[(size_t)r * TDIM + c]       = v0;
                    *(float2*)&ob[(size_t)(r + 8) * TDIM + c] = v1;
                }
            }
        }

        // prefetch tile i+2 into stage (st+2)%3 (safe: != st and != st+1)
        if (t + 2 * GEMM_GRID < NTILES)
            load_tiles((st + 2) % NSTAGE, t + 2 * GEMM_GRID);

        st = (st + 1) % NSTAGE;
        t += GEMM_GRID;
    }
}

extern "C" void kernel_launch(void* const* d_in, const int* in_sizes, int n_in,
                              void* d_out, int out_size) {
    const float* A = (const float*)d_in[0];
    const float* B = (const float*)d_in[1];
    float* out = (float*)d_out;

    cudaFuncSetAttribute(k_gemm, cudaFuncAttributeMaxDynamicSharedMemorySize, SMEM_DYN);

    k_minmax<<<dim3(MM_BLOCKS, 1, 2), 256>>>(A, B);
    k_quant<<<dim3(2048, 1, 2), 256>>>(A, B);
    k_gemm<<<GEMM_GRID, 256, SMEM_DYN>>>(out);
}